// round 16
// baseline (speedup 1.0000x reference)
#include <cuda_runtime.h>
#include <cstdint>

typedef unsigned long long ULL;
typedef unsigned char u8;
typedef unsigned int u32;

// ---------------- problem dims ----------------
#define T_  4
#define B_  8
#define S_  1024
#define D_  768
#define HF_ 3072
#define SD_   (S_*D_)
#define SH_   (S_*HF_)
#define BSD_  (B_*SD_)
#define BSH_  (B_*SH_)
#define TBSD_ (T_*BSD_)
#define TBSH_ (T_*BSH_)
#define TBD_  (T_*B_*D_)
#define BD_   (B_*D_)
#define MROWS_ (T_*B_*S_)

#define KC_  256   // Eigen gebp k-panel (confirmed R4)
#define KS_  32    // k per GEMM pipeline stage (1 mask word)

// bn-stat stages
#define ST_Q   0
#define ST_V   1
#define ST_K   2
#define ST_ATT 3
#define ST_O1  4
#define ST_O2  5

// ---------------- device scratch ----------------
__device__ u8    g_sp  [TBSD_];
__device__ float g_q   [TBSD_];
__device__ float g_k   [TBSD_];
__device__ float g_v   [TBSD_];
__device__ u8    g_qs  [TBSD_];
__device__ u8    g_ks  [TBSD_];
__device__ u8    g_vs  [TBSD_];
__device__ float g_att [TBSD_];
__device__ float g_h   [TBSD_];
__device__ float g_o1  [TBSH_];
__device__ float g_o2  [TBSD_];
__device__ int   g_qkp [4*TBD_];
__device__ u8    g_qks [TBD_];
__device__ float g_part[8*512];
__device__ float g_mean [6*8];
__device__ float g_denom[6*8];

// bitmasks, TRANSPOSED: [k/32][M] (contiguous in M for cp.async)
__device__ u32 g_msk_sp  [(D_/32)*MROWS_];
__device__ u32 g_msk_qkvm[(D_/32)*MROWS_];
__device__ u32 g_msk_sp2 [(D_/32)*MROWS_];
__device__ u32 g_msk_s1  [(HF_/32)*MROWS_];

// pointer tables (capture-safe: host never queries symbols)
__device__ u32*   g_ptrM[4];
__device__ float* g_ptrF[6];
__global__ void k_init_ptrs() {
    if (threadIdx.x == 0 && blockIdx.x == 0) {
        g_ptrM[0] = g_msk_sp; g_ptrM[1] = g_msk_qkvm; g_ptrM[2] = g_msk_sp2; g_ptrM[3] = g_msk_s1;
        g_ptrF[0] = g_q;   g_ptrF[1] = g_k;    g_ptrF[2] = g_v;
        g_ptrF[3] = g_att; g_ptrF[4] = g_o1;   g_ptrF[5] = g_o2;
    }
}

// ---------------- f32x2 helpers (bitwise 2x IEEE fp32 ops) ----------------
__device__ __forceinline__ ULL add2(ULL a, ULL b) {
    ULL r; asm("add.rn.f32x2 %0, %1, %2;" : "=l"(r) : "l"(a), "l"(b)); return r;
}
__device__ __forceinline__ float2 unpack2(ULL v) {
    float2 r; asm("mov.b64 {%0, %1}, %2;" : "=f"(r.x), "=f"(r.y) : "l"(v)); return r;
}

// ---------------- cp.async helpers ----------------
__device__ __forceinline__ void cp_async16(uint32_t smem, const void* g) {
    asm volatile("cp.async.cg.shared.global [%0], [%1], 16;" :: "r"(smem), "l"(g));
}
__device__ __forceinline__ void cp_commit() {
    asm volatile("cp.async.commit_group;");
}
__device__ __forceinline__ void cp_wait0() {
    asm volatile("cp.async.wait_group 0;");
}

// ---------------- sparse spike GEMM (sgemm11) ----------------
// C[M,N] = spikes(A) @ B[K,N] (+bias), A given as bitmasks MaskT[k/32][M].
// BITWISE identical to the Eigen-emulating dense chain: per output, ascending-k
// FADD of B[k][n] for set bits only (skipped k's are exact identities).
// Panels of 256 k combined by FADD in ascending order, bias last.
// Tile 64x128, 512 threads: warp = 4 rows, lane = 4 cols.
// Single while-loop over all 4 rows with PER-ROW UNIFORM PREDICATION:
// masks are warp-uniform, so `if (w)` is a uniform branch/predicate — a
// predicated-off LDS generates no crossbar wavefronts -> zero dummy traffic,
// and 4 independent LDS->FADD chains stay in flight.
// 2 blocks/SM (regs capped 64). ONE __syncthreads per stage.
__global__ __launch_bounds__(512, 2)
void sgemm11(int aSel, const float* __restrict__ Bm, const float* __restrict__ bias,
             int cSel, int N, int K)
{
    __shared__ __align__(16) float Bs[2][34][128];  // rows 1..32 = B slab (row 0 unused pad)
    __shared__ __align__(16) u32  Msm[2][64];

    const u32* __restrict__ Mt = g_ptrM[aSel];
    float* __restrict__ C = g_ptrF[cSel];

    const int tid  = threadIdx.x;
    const int wid  = tid >> 5;          // 0..15
    const int lane = tid & 31;
    const int bn = blockIdx.x, bm = blockIdx.y;
    const int lane4 = lane * 4;

    // copy mapping: 32 rows x 128 cols per stage -> smem rows 1..32
    const int crow = tid >> 4;          // 0..31
    const int cch  = (tid & 15) * 8;    // float offset, 0..120 step 8 (32B)

    uint32_t sB0 = (uint32_t)__cvta_generic_to_shared(&Bs[0][crow + 1][cch]);
    uint32_t sB1 = (uint32_t)__cvta_generic_to_shared(&Bs[1][crow + 1][cch]);
    uint32_t sM0 = (uint32_t)__cvta_generic_to_shared(&Msm[0][0]);
    uint32_t sM1 = (uint32_t)__cvta_generic_to_shared(&Msm[1][0]);

    const int S = K / KS_;

    // prologue: copy stage 0
    {
        const float* src = Bm + (size_t)crow * N + bn * 128 + cch;
        cp_async16(sB0, src);
        cp_async16(sB0 + 16, src + 4);
        if (tid < 16)
            cp_async16(sM0 + tid * 16, Mt + bm * 64 + tid * 4);
        cp_commit();
    }

    ULL acc[4][2], part[4][2];
#pragma unroll
    for (int r = 0; r < 4; r++) {
        acc[r][0] = 0ULL; acc[r][1] = 0ULL;
        part[r][0] = 0ULL; part[r][1] = 0ULL;
    }

    for (int s = 0; s < S; s++) {
        const int buf = s & 1;
        cp_wait0();
        __syncthreads();

        // issue next stage's copy into the other buffer (safe: all warps have
        // finished computing on buf^1 by passing the sync above)
        if (s + 1 < S) {
            const int k0 = (s + 1) * KS_;
            const float* src = Bm + (size_t)(k0 + crow) * N + bn * 128 + cch;
            uint32_t dB = buf ? sB0 : sB1;
            cp_async16(dB, src);
            cp_async16(dB + 16, src + 4);
            if (tid < 16)
                cp_async16((buf ? sM0 : sM1) + tid * 16,
                           Mt + (size_t)(s + 1) * MROWS_ + bm * 64 + tid * 4);
            cp_commit();
        }

        {
            u32 w0 = Msm[buf][wid * 4 + 0];
            u32 w1 = Msm[buf][wid * 4 + 1];
            u32 w2 = Msm[buf][wid * 4 + 2];
            u32 w3 = Msm[buf][wid * 4 + 3];
            ULL a00 = part[0][0], a01 = part[0][1];
            ULL a10 = part[1][0], a11 = part[1][1];
            ULL a20 = part[2][0], a21 = part[2][1];
            ULL a30 = part[3][0], a31 = part[3][1];
            while (w0 | w1 | w2 | w3) {
                if (w0) {
                    int k = __ffs(w0); w0 &= w0 - 1;
                    ulonglong2 v = *(const ulonglong2*)&Bs[buf][k][lane4];
                    a00 = add2(a00, v.x); a01 = add2(a01, v.y);
                }
                if (w1) {
                    int k = __ffs(w1); w1 &= w1 - 1;
                    ulonglong2 v = *(const ulonglong2*)&Bs[buf][k][lane4];
                    a10 = add2(a10, v.x); a11 = add2(a11, v.y);
                }
                if (w2) {
                    int k = __ffs(w2); w2 &= w2 - 1;
                    ulonglong2 v = *(const ulonglong2*)&Bs[buf][k][lane4];
                    a20 = add2(a20, v.x); a21 = add2(a21, v.y);
                }
                if (w3) {
                    int k = __ffs(w3); w3 &= w3 - 1;
                    ulonglong2 v = *(const ulonglong2*)&Bs[buf][k][lane4];
                    a30 = add2(a30, v.x); a31 = add2(a31, v.y);
                }
            }
            part[0][0] = a00; part[0][1] = a01;
            part[1][0] = a10; part[1][1] = a11;
            part[2][0] = a20; part[2][1] = a21;
            part[3][0] = a30; part[3][1] = a31;
        }

        // Eigen panel boundary (every 256 k): FADD-flush part into acc
        if (((s + 1) & 7) == 0) {
#pragma unroll
            for (int r = 0; r < 4; r++) {
                acc[r][0] = add2(acc[r][0], part[r][0]); part[r][0] = 0ULL;
                acc[r][1] = add2(acc[r][1], part[r][1]); part[r][1] = 0ULL;
            }
        }
    }

    float bb[4];
#pragma unroll
    for (int j = 0; j < 4; j++)
        bb[j] = bias ? bias[bn * 128 + lane4 + j] : 0.0f;

#pragma unroll
    for (int r = 0; r < 4; r++) {
        int row = bm * 64 + wid * 4 + r;
        float2 q0 = unpack2(acc[r][0]), q1 = unpack2(acc[r][1]);
        *(float4*)(C + (size_t)row * N + bn * 128 + lane4) =
            make_float4(q0.x + bb[0], q0.y + bb[1], q1.x + bb[2], q1.y + bb[3]);
    }
}

// ---------------- IF on input x -> sp bytes + fused mask pack ----------------
__global__ void k_ifx(const float* __restrict__ x) {
    int j = blockIdx.x * 256 + threadIdx.x;
    if (j >= BSD_) return;
    int lane = threadIdx.x & 31;
    int row = j / D_;              // b*S + s
    int kw  = (j % D_) >> 5;
    float vm = 0.0f;
#pragma unroll
    for (int t = 0; t < T_; t++) {
        int idx = t * BSD_ + j;
        vm += x[idx];
        float s = (vm >= 1.0f) ? 1.0f : 0.0f;
        u8 sb = (u8)s;
        g_sp[idx] = sb;
        u32 bal = __ballot_sync(0xffffffffu, sb != 0);
        if (lane == 0) g_msk_sp[(size_t)kw * MROWS_ + t * (B_ * S_) + row] = bal;
        vm *= (1.0f - s);
    }
}

// ---------------- BN pass A: per-batch sum -> mean ----------------
// Iteration order identical to the original i-strided loop (bit-exact).
__global__ void k_redA(int sel, int SDv) {
    const float* __restrict__ X = g_ptrF[sel];
    int b = blockIdx.y;
    int base = blockIdx.x * 256 + threadIdx.x;
    int J = SDv >> 17;   // SDv / 131072 : 6 (D) or 24 (HF)
    float s = 0.0f;
    for (int t = 0; t < T_; t++) {
        const float* Xb = X + (size_t)(t * B_ + b) * SDv;
        for (int j = 0; j < J; j++)
            s += Xb[base + (j << 17)];
    }
    __shared__ float sh[256];
    int tid = threadIdx.x;
    sh[tid] = s; __syncthreads();
    for (int o = 128; o > 0; o >>= 1) { if (tid < o) sh[tid] += sh[tid + o]; __syncthreads(); }
    if (tid == 0) g_part[b * 512 + blockIdx.x] = sh[0];
}

__global__ void k_finA(int SDv, int stage) {
    int b = blockIdx.x, tid = threadIdx.x;
    double s = (double)g_part[b * 512 + tid] + (double)g_part[b * 512 + tid + 256];
    __shared__ double sh[256];
    sh[tid] = s; __syncthreads();
    for (int o = 128; o > 0; o >>= 1) { if (tid < o) sh[tid] += sh[tid + o]; __syncthreads(); }
    if (tid == 0) {
        float E = (float)(T_ * SDv);
        g_mean[stage * 8 + b] = __fdiv_rn((float)sh[0], E);
    }
}

// ---------------- BN pass B: per-batch sum of (x-m)^2 -> denom ----------------
__global__ void k_redB(int sel, int SDv, int stage) {
    const float* __restrict__ X = g_ptrF[sel];
    int b = blockIdx.y;
    float m = g_mean[stage * 8 + b];
    int base = blockIdx.x * 256 + threadIdx.x;
    int J = SDv >> 17;
    float s = 0.0f;
    for (int t = 0; t < T_; t++) {
        const float* Xb = X + (size_t)(t * B_ + b) * SDv;
        for (int j = 0; j < J; j++) {
            float v = Xb[base + (j << 17)] - m;
            s += v * v;
        }
    }
    __shared__ float sh[256];
    int tid = threadIdx.x;
    sh[tid] = s; __syncthreads();
    for (int o = 128; o > 0; o >>= 1) { if (tid < o) sh[tid] += sh[tid + o]; __syncthreads(); }
    if (tid == 0) g_part[b * 512 + blockIdx.x] = sh[0];
}

__global__ void k_finB(int SDv, int stage) {
    int b = blockIdx.x, tid = threadIdx.x;
    double s = (double)g_part[b * 512 + tid] + (double)g_part[b * 512 + tid + 256];
    __shared__ double sh[256];
    sh[tid] = s; __syncthreads();
    for (int o = 128; o > 0; o >>= 1) { if (tid < o) sh[tid] += sh[tid + o]; __syncthreads(); }
    if (tid == 0) {
        float E = (float)(T_ * SDv);
        float var_f = __fdiv_rn((float)sh[0], E);
        g_denom[stage * 8 + b] = __fsqrt_rn(var_f + 1e-5f);
    }
}

// ---------------- fused BN + IF over Q,V,K with CARRIED membrane ----------------
__global__ void k_ifqvk() {
    int j = blockIdx.x * 256 + threadIdx.x;
    if (j >= BSD_) return;
    int b = j / SD_;
    float mq = g_mean[ST_Q * 8 + b], dq = g_denom[ST_Q * 8 + b];
    float mv = g_mean[ST_V * 8 + b], dv = g_denom[ST_V * 8 + b];
    float mk = g_mean[ST_K * 8 + b], dk = g_denom[ST_K * 8 + b];
    float vm = 0.0f;
#pragma unroll
    for (int t = 0; t < T_; t++) {
        int idx = t * BSD_ + j;
        vm += __fdiv_rn(g_q[idx] - mq, dq);
        float s = (vm >= 1.0f) ? 1.0f : 0.0f;
        g_qs[idx] = (u8)s;
        vm *= (1.0f - s);
    }
#pragma unroll
    for (int t = 0; t < T_; t++) {
        int idx = t * BSD_ + j;
        vm += __fdiv_rn(g_v[idx] - mv, dv);
        float s = (vm >= 1.0f) ? 1.0f : 0.0f;
        g_vs[idx] = (u8)s;
        vm *= (1.0f - s);
    }
#pragma unroll
    for (int t = 0; t < T_; t++) {
        int idx = t * BSD_ + j;
        vm += __fdiv_rn(g_k[idx] - mk, dk);
        float s = (vm >= 1.0f) ? 1.0f : 0.0f;
        g_ks[idx] = (u8)s;
        vm *= (1.0f - s);
    }
}

// ---------------- QK: integer seq-reduction (exact) ----------------
__global__ void k_qk() {
    int d = blockIdx.x * 256 + threadIdx.x;
    int tb = blockIdx.y;
    int sp = blockIdx.z;
    int acc = 0;
    int s0 = sp * 256;
    for (int s = s0; s < s0 + 256; s++) {
        size_t idx = ((size_t)tb * S_ + s) * D_ + d;
        acc += (int)(g_qs[idx] & g_ks[idx]);
    }
    g_qkp[sp * TBD_ + tb * D_ + d] = acc;
}

// QKs = IF(QK) over t (integers exact in fp32)
__global__ void k_qks() {
    int i = blockIdx.x * 256 + threadIdx.x;
    if (i >= BD_) return;
    int b = i / D_, d = i - b * D_;
    float vm = 0.0f;
#pragma unroll
    for (int t = 0; t < T_; t++) {
        int idx = (t * B_ + b) * D_ + d;
        int qk = g_qkp[idx] + g_qkp[TBD_ + idx] + g_qkp[2 * TBD_ + idx] +
                 g_qkp[3 * TBD_ + idx];
        vm += (float)qk;
        float s = (vm >= 1.0f) ? 1.0f : 0.0f;
        g_qks[idx] = (u8)s;
        vm *= (1.0f - s);
    }
}

// QKV spikes = Vs & QKs, mask emitted directly
__global__ void k_qkvm() {
    int idx = blockIdx.x * 256 + threadIdx.x;
    if (idx >= TBSD_) return;
    int lane = threadIdx.x & 31;
    int d = idx % D_;
    int tb = idx / SD_;           // t*B + b
    u8 v = g_vs[idx] & g_qks[tb * D_ + d];
    u32 bal = __ballot_sync(0xffffffffu, v != 0);
    if (lane == 0) {
        int m = idx / D_;         // == t*B*S + b*S + s
        int kw = d >> 5;
        g_msk_qkvm[(size_t)kw * MROWS_ + m] = bal;
    }
}

// h = sp + bn(att); sp2 = IF(h), mask emitted directly
__global__ void k_hsp2() {
    int j = blockIdx.x * 256 + threadIdx.x;
    if (j >= BSD_) return;
    int lane = threadIdx.x & 31;
    int b = j / SD_;
    int row = j / D_;
    int kw = (j % D_) >> 5;
    float m = g_mean[ST_ATT * 8 + b], dn = g_denom[ST_ATT * 8 + b];
    float vm = 0.0f;
#pragma unroll
    for (int t = 0; t < T_; t++) {
        int idx = t * BSD_ + j;
        float hval = (float)g_sp[idx] + __fdiv_rn(g_att[idx] - m, dn);
        g_h[idx] = hval;
        vm += hval;
        float s = (vm >= 1.0f) ? 1.0f : 0.0f;
        u32 bal = __ballot_sync(0xffffffffu, s != 0.0f);
        if (lane == 0) g_msk_sp2[(size_t)kw * MROWS_ + t * (B_ * S_) + row] = bal;
        vm *= (1.0f - s);
    }
}

// s1 = IF(bn(o1)), mask emitted directly
__global__ void k_s1() {
    int j = blockIdx.x * 256 + threadIdx.x;
    if (j >= BSH_) return;
    int lane = threadIdx.x & 31;
    int b = j / SH_;
    int row = j / HF_;
    int kw = (j % HF_) >> 5;
    float m = g_mean[ST_O1 * 8 + b], dn = g_denom[ST_O1 * 8 + b];
    float vm = 0.0f;
#pragma unroll
    for (int t = 0; t < T_; t++) {
        int idx = t * BSH_ + j;
        vm += __fdiv_rn(g_o1[idx] - m, dn);
        float s = (vm >= 1.0f) ? 1.0f : 0.0f;
        u32 bal = __ballot_sync(0xffffffffu, s != 0.0f);
        if (lane == 0) g_msk_s1[(size_t)kw * MROWS_ + t * (B_ * S_) + row] = bal;
        vm *= (1.0f - s);
    }
}

// out = h + bn(o2), float4
__global__ void k_out(float* __restrict__ out) {
    int idx4 = blockIdx.x * 256 + threadIdx.x;
    if (idx4 >= TBSD_ / 4) return;
    int idx = idx4 * 4;
    int b = (idx / SD_) % B_;
    float m = g_mean[ST_O2 * 8 + b], dn = g_denom[ST_O2 * 8 + b];
    float4 hv = *(const float4*)(g_h + idx);
    float4 ov = *(const float4*)(g_o2 + idx);
    float4 r;
    r.x = hv.x + __fdiv_rn(ov.x - m, dn);
    r.y = hv.y + __fdiv_rn(ov.y - m, dn);
    r.z = hv.z + __fdiv_rn(ov.z - m, dn);
    r.w = hv.w + __fdiv_rn(ov.w - m, dn);
    *(float4*)(out + idx) = r;
}

// ---------------- launch (kernel launches ONLY — capture-safe) ----------------
extern "C" void kernel_launch(void* const* d_in, const int* in_sizes, int n_in,
                              void* d_out, int out_size) {
    (void)in_sizes; (void)n_in; (void)out_size;
    const float* x  = (const float*)d_in[0];
    const float* wq = (const float*)d_in[1];
    const float* wk = (const float*)d_in[2];
    const float* wv = (const float*)d_in[3];
    const float* wo = (const float*)d_in[4];
    const float* w1 = (const float*)d_in[5];
    const float* b1 = (const float*)d_in[6];
    const float* w2 = (const float*)d_in[7];
    const float* b2 = (const float*)d_in[8];
    float* out = (float*)d_out;

    const int EW = 256;
    k_init_ptrs<<<1, 32>>>();

    // 1) sp = IF(x) + mask pack (fused)
    k_ifx<<<BSD_ / EW, EW>>>(x);

    // 2) Q,K,V sparse GEMMs (64-row tiles)
    sgemm11<<<dim3(6, 512), 512>>>(0, wq, nullptr, 0, D_, D_);
    sgemm11<<<dim3(6, 512), 512>>>(0, wk, nullptr, 1, D_, D_);
    sgemm11<<<dim3(6, 512), 512>>>(0, wv, nullptr, 2, D_, D_);

    // 3) BN stats (two-pass) for Q, V, K
    k_redA<<<dim3(512, 8), 256>>>(0, SD_); k_finA<<<8, 256>>>(SD_, ST_Q);
    k_redB<<<dim3(512, 8), 256>>>(0, SD_, ST_Q); k_finB<<<8, 256>>>(SD_, ST_Q);
    k_redA<<<dim3(512, 8), 256>>>(2, SD_); k_finA<<<8, 256>>>(SD_, ST_V);
    k_redB<<<dim3(512, 8), 256>>>(2, SD_, ST_V); k_finB<<<8, 256>>>(SD_, ST_V);
    k_redA<<<dim3(512, 8), 256>>>(1, SD_); k_finA<<<8, 256>>>(SD_, ST_K);
    k_redB<<<dim3(512, 8), 256>>>(1, SD_, ST_K); k_finB<<<8, 256>>>(SD_, ST_K);

    // 4) fused BN+IF, membrane carried Q -> V -> K
    k_ifqvk<<<BSD_ / EW, EW>>>();

    // 5) QK (integer) + IF + QKV spike mask (fused pack)
    k_qk<<<dim3(D_ / 256, T_ * B_, 4), 256>>>();
    k_qks<<<BD_ / EW, EW>>>();
    k_qkvm<<<TBSD_ / EW, EW>>>();

    // 6) att = QKV @ wo + BN stats
    sgemm11<<<dim3(6, 512), 512>>>(1, wo, nullptr, 3, D_, D_);
    k_redA<<<dim3(512, 8), 256>>>(3, SD_); k_finA<<<8, 256>>>(SD_, ST_ATT);
    k_redB<<<dim3(512, 8), 256>>>(3, SD_, ST_ATT); k_finB<<<8, 256>>>(SD_, ST_ATT);

    // 7) h = sp + bn(att); sp2 = IF(h) + mask pack (fused)
    k_hsp2<<<BSD_ / EW, EW>>>();

    // 8) o1 = sp2 @ w1 + b1; BN; s1 = IF(bn(o1)) + mask pack (fused)
    sgemm11<<<dim3(24, 512), 512>>>(2, w1, b1, 4, HF_, D_);
    k_redA<<<dim3(512, 8), 256>>>(4, SH_); k_finA<<<8, 256>>>(SH_, ST_O1);
    k_redB<<<dim3(512, 8), 256>>>(4, SH_, ST_O1); k_finB<<<8, 256>>>(SH_, ST_O1);
    k_s1<<<BSH_ / EW, EW>>>();

    // 9) o2 = s1 @ w2 + b2; BN
    sgemm11<<<dim3(6, 512), 512>>>(3, w2, b2, 5, D_, HF_);
    k_redA<<<dim3(512, 8), 256>>>(5, SD_); k_finA<<<8, 256>>>(SD_, ST_O2);
    k_redB<<<dim3(512, 8), 256>>>(5, SD_, ST_O2); k_finB<<<8, 256>>>(SD_, ST_O2);

    // 10) out = h + bn(o2)
    k_out<<<TBSD_ / (EW * 4), EW>>>(out);
}

// round 17
// speedup vs baseline: 1.3266x; 1.3266x over previous
#include <cuda_runtime.h>
#include <cstdint>

typedef unsigned long long ULL;
typedef unsigned char u8;
typedef unsigned int u32;

// ---------------- problem dims ----------------
#define T_  4
#define B_  8
#define S_  1024
#define D_  768
#define HF_ 3072
#define SD_   (S_*D_)
#define SH_   (S_*HF_)
#define BSD_  (B_*SD_)
#define BSH_  (B_*SH_)
#define TBSD_ (T_*BSD_)
#define TBSH_ (T_*BSH_)
#define TBD_  (T_*B_*D_)
#define BD_   (B_*D_)
#define MROWS_ (T_*B_*S_)

#define KC_  256   // Eigen gebp k-panel (confirmed R4)
#define KS_  32    // k per GEMM pipeline stage (1 mask word)

// bn-stat stages
#define ST_Q   0
#define ST_V   1
#define ST_K   2
#define ST_ATT 3
#define ST_O1  4
#define ST_O2  5

// ---------------- device scratch ----------------
__device__ u8    g_sp  [TBSD_];
__device__ float g_q   [TBSD_];
__device__ float g_k   [TBSD_];
__device__ float g_v   [TBSD_];
__device__ u8    g_qs  [TBSD_];
__device__ u8    g_ks  [TBSD_];
__device__ u8    g_vs  [TBSD_];
__device__ float g_att [TBSD_];
__device__ float g_h   [TBSD_];
__device__ float g_o1  [TBSH_];
__device__ float g_o2  [TBSD_];
__device__ int   g_qkp [4*TBD_];
__device__ u8    g_qks [TBD_];
__device__ float g_part[8*512];
__device__ float g_mean [6*8];
__device__ float g_denom[6*8];

// bitmasks, TRANSPOSED: [k/32][M] (contiguous in M for cp.async)
__device__ u32 g_msk_sp  [(D_/32)*MROWS_];
__device__ u32 g_msk_qkvm[(D_/32)*MROWS_];
__device__ u32 g_msk_sp2 [(D_/32)*MROWS_];
__device__ u32 g_msk_s1  [(HF_/32)*MROWS_];

// pointer tables (capture-safe: host never queries symbols)
__device__ u32*   g_ptrM[4];
__device__ float* g_ptrF[6];
__global__ void k_init_ptrs() {
    if (threadIdx.x == 0 && blockIdx.x == 0) {
        g_ptrM[0] = g_msk_sp; g_ptrM[1] = g_msk_qkvm; g_ptrM[2] = g_msk_sp2; g_ptrM[3] = g_msk_s1;
        g_ptrF[0] = g_q;   g_ptrF[1] = g_k;    g_ptrF[2] = g_v;
        g_ptrF[3] = g_att; g_ptrF[4] = g_o1;   g_ptrF[5] = g_o2;
    }
}

// ---------------- f32x2 helpers (bitwise 2x IEEE fp32 ops) ----------------
__device__ __forceinline__ ULL add2(ULL a, ULL b) {
    ULL r; asm("add.rn.f32x2 %0, %1, %2;" : "=l"(r) : "l"(a), "l"(b)); return r;
}
__device__ __forceinline__ float2 unpack2(ULL v) {
    float2 r; asm("mov.b64 {%0, %1}, %2;" : "=f"(r.x), "=f"(r.y) : "l"(v)); return r;
}

// ---------------- cp.async helpers ----------------
__device__ __forceinline__ void cp_async16(uint32_t smem, const void* g) {
    asm volatile("cp.async.cg.shared.global [%0], [%1], 16;" :: "r"(smem), "l"(g));
}
__device__ __forceinline__ void cp_commit() {
    asm volatile("cp.async.commit_group;");
}
__device__ __forceinline__ void cp_wait0() {
    asm volatile("cp.async.wait_group 0;");
}

// ---------------- sparse spike GEMM (sgemm12) ----------------
// C[M,N] = spikes(A) @ B[K,N] (+bias), A given as bitmasks MaskT[k/32][M].
// BITWISE identical to the Eigen-emulating dense chain: per output, ascending-k
// FADD of B[k][n] for set bits only (skipped k's are exact identities).
// Panels of 256 k combined by FADD in ascending order, bias last.
// Tile 64x128, 512 threads: warp = 4 rows (2 pairs), lane = 4 cols.
// Per pair: MIN-loop (both rows active, 2 unconditional loads, no per-iter
// branching beyond the loop branch) + DRAIN-loops for the longer row.
// Loads = popc0 + popc1 exactly: zero dummy crossbar traffic AND zero
// BSSY/BSYNC-wrapped conditional arms (the R16 mistake).
// 2 blocks/SM (regs capped 64). ONE __syncthreads per stage.
__global__ __launch_bounds__(512, 2)
void sgemm12(int aSel, const float* __restrict__ Bm, const float* __restrict__ bias,
             int cSel, int N, int K)
{
    __shared__ __align__(16) float Bs[2][34][128];  // rows 1..32 = B slab (row 0 pad)
    __shared__ __align__(16) u32  Msm[2][64];

    const u32* __restrict__ Mt = g_ptrM[aSel];
    float* __restrict__ C = g_ptrF[cSel];

    const int tid  = threadIdx.x;
    const int wid  = tid >> 5;          // 0..15
    const int lane = tid & 31;
    const int bn = blockIdx.x, bm = blockIdx.y;
    const int lane4 = lane * 4;

    // copy mapping: 32 rows x 128 cols per stage -> smem rows 1..32
    const int crow = tid >> 4;          // 0..31
    const int cch  = (tid & 15) * 8;    // float offset, 0..120 step 8 (32B)

    uint32_t sB0 = (uint32_t)__cvta_generic_to_shared(&Bs[0][crow + 1][cch]);
    uint32_t sB1 = (uint32_t)__cvta_generic_to_shared(&Bs[1][crow + 1][cch]);
    uint32_t sM0 = (uint32_t)__cvta_generic_to_shared(&Msm[0][0]);
    uint32_t sM1 = (uint32_t)__cvta_generic_to_shared(&Msm[1][0]);

    const int S = K / KS_;

    // prologue: copy stage 0
    {
        const float* src = Bm + (size_t)crow * N + bn * 128 + cch;
        cp_async16(sB0, src);
        cp_async16(sB0 + 16, src + 4);
        if (tid < 16)
            cp_async16(sM0 + tid * 16, Mt + bm * 64 + tid * 4);
        cp_commit();
    }

    ULL acc[4][2], part[4][2];
#pragma unroll
    for (int r = 0; r < 4; r++) {
        acc[r][0] = 0ULL; acc[r][1] = 0ULL;
        part[r][0] = 0ULL; part[r][1] = 0ULL;
    }

    for (int s = 0; s < S; s++) {
        const int buf = s & 1;
        cp_wait0();
        __syncthreads();

        // issue next stage's copy into the other buffer (safe: all warps have
        // finished computing on buf^1 by passing the sync above)
        if (s + 1 < S) {
            const int k0 = (s + 1) * KS_;
            const float* src = Bm + (size_t)(k0 + crow) * N + bn * 128 + cch;
            uint32_t dB = buf ? sB0 : sB1;
            cp_async16(dB, src);
            cp_async16(dB + 16, src + 4);
            if (tid < 16)
                cp_async16((buf ? sM0 : sM1) + tid * 16,
                           Mt + (size_t)(s + 1) * MROWS_ + bm * 64 + tid * 4);
            cp_commit();
        }

#pragma unroll
        for (int rp = 0; rp < 2; rp++) {
            u32 w0 = Msm[buf][wid * 4 + 2 * rp];
            u32 w1 = Msm[buf][wid * 4 + 2 * rp + 1];
            ULL a00 = part[2 * rp][0],     a01 = part[2 * rp][1];
            ULL a10 = part[2 * rp + 1][0], a11 = part[2 * rp + 1][1];
            // main: both rows active (2 independent chains, no cond. arms)
            while (w0 && w1) {
                int k0 = __ffs(w0); w0 &= w0 - 1;
                int k1 = __ffs(w1); w1 &= w1 - 1;
                ulonglong2 v0 = *(const ulonglong2*)&Bs[buf][k0][lane4];
                ulonglong2 v1 = *(const ulonglong2*)&Bs[buf][k1][lane4];
                a00 = add2(a00, v0.x); a01 = add2(a01, v0.y);
                a10 = add2(a10, v1.x); a11 = add2(a11, v1.y);
            }
            // drain row 0
            while (w0) {
                int k0 = __ffs(w0); w0 &= w0 - 1;
                ulonglong2 v0 = *(const ulonglong2*)&Bs[buf][k0][lane4];
                a00 = add2(a00, v0.x); a01 = add2(a01, v0.y);
            }
            // drain row 1
            while (w1) {
                int k1 = __ffs(w1); w1 &= w1 - 1;
                ulonglong2 v1 = *(const ulonglong2*)&Bs[buf][k1][lane4];
                a10 = add2(a10, v1.x); a11 = add2(a11, v1.y);
            }
            part[2 * rp][0] = a00;     part[2 * rp][1] = a01;
            part[2 * rp + 1][0] = a10; part[2 * rp + 1][1] = a11;
        }

        // Eigen panel boundary (every 256 k): FADD-flush part into acc
        if (((s + 1) & 7) == 0) {
#pragma unroll
            for (int r = 0; r < 4; r++) {
                acc[r][0] = add2(acc[r][0], part[r][0]); part[r][0] = 0ULL;
                acc[r][1] = add2(acc[r][1], part[r][1]); part[r][1] = 0ULL;
            }
        }
    }

    float bb[4];
#pragma unroll
    for (int j = 0; j < 4; j++)
        bb[j] = bias ? bias[bn * 128 + lane4 + j] : 0.0f;

#pragma unroll
    for (int r = 0; r < 4; r++) {
        int row = bm * 64 + wid * 4 + r;
        float2 q0 = unpack2(acc[r][0]), q1 = unpack2(acc[r][1]);
        *(float4*)(C + (size_t)row * N + bn * 128 + lane4) =
            make_float4(q0.x + bb[0], q0.y + bb[1], q1.x + bb[2], q1.y + bb[3]);
    }
}

// ---------------- IF on input x -> sp bytes + fused mask pack ----------------
__global__ void k_ifx(const float* __restrict__ x) {
    int j = blockIdx.x * 256 + threadIdx.x;
    if (j >= BSD_) return;
    int lane = threadIdx.x & 31;
    int row = j / D_;              // b*S + s
    int kw  = (j % D_) >> 5;
    float vm = 0.0f;
#pragma unroll
    for (int t = 0; t < T_; t++) {
        int idx = t * BSD_ + j;
        vm += x[idx];
        float s = (vm >= 1.0f) ? 1.0f : 0.0f;
        u8 sb = (u8)s;
        g_sp[idx] = sb;
        u32 bal = __ballot_sync(0xffffffffu, sb != 0);
        if (lane == 0) g_msk_sp[(size_t)kw * MROWS_ + t * (B_ * S_) + row] = bal;
        vm *= (1.0f - s);
    }
}

// ---------------- BN pass A: per-batch sum -> mean ----------------
// Iteration order identical to the original i-strided loop (bit-exact).
__global__ void k_redA(int sel, int SDv) {
    const float* __restrict__ X = g_ptrF[sel];
    int b = blockIdx.y;
    int base = blockIdx.x * 256 + threadIdx.x;
    int J = SDv >> 17;   // SDv / 131072 : 6 (D) or 24 (HF)
    float s = 0.0f;
    for (int t = 0; t < T_; t++) {
        const float* Xb = X + (size_t)(t * B_ + b) * SDv;
        for (int j = 0; j < J; j++)
            s += Xb[base + (j << 17)];
    }
    __shared__ float sh[256];
    int tid = threadIdx.x;
    sh[tid] = s; __syncthreads();
    for (int o = 128; o > 0; o >>= 1) { if (tid < o) sh[tid] += sh[tid + o]; __syncthreads(); }
    if (tid == 0) g_part[b * 512 + blockIdx.x] = sh[0];
}

__global__ void k_finA(int SDv, int stage) {
    int b = blockIdx.x, tid = threadIdx.x;
    double s = (double)g_part[b * 512 + tid] + (double)g_part[b * 512 + tid + 256];
    __shared__ double sh[256];
    sh[tid] = s; __syncthreads();
    for (int o = 128; o > 0; o >>= 1) { if (tid < o) sh[tid] += sh[tid + o]; __syncthreads(); }
    if (tid == 0) {
        float E = (float)(T_ * SDv);
        g_mean[stage * 8 + b] = __fdiv_rn((float)sh[0], E);
    }
}

// ---------------- BN pass B: per-batch sum of (x-m)^2 -> denom ----------------
__global__ void k_redB(int sel, int SDv, int stage) {
    const float* __restrict__ X = g_ptrF[sel];
    int b = blockIdx.y;
    float m = g_mean[stage * 8 + b];
    int base = blockIdx.x * 256 + threadIdx.x;
    int J = SDv >> 17;
    float s = 0.0f;
    for (int t = 0; t < T_; t++) {
        const float* Xb = X + (size_t)(t * B_ + b) * SDv;
        for (int j = 0; j < J; j++) {
            float v = Xb[base + (j << 17)] - m;
            s += v * v;
        }
    }
    __shared__ float sh[256];
    int tid = threadIdx.x;
    sh[tid] = s; __syncthreads();
    for (int o = 128; o > 0; o >>= 1) { if (tid < o) sh[tid] += sh[tid + o]; __syncthreads(); }
    if (tid == 0) g_part[b * 512 + blockIdx.x] = sh[0];
}

__global__ void k_finB(int SDv, int stage) {
    int b = blockIdx.x, tid = threadIdx.x;
    double s = (double)g_part[b * 512 + tid] + (double)g_part[b * 512 + tid + 256];
    __shared__ double sh[256];
    sh[tid] = s; __syncthreads();
    for (int o = 128; o > 0; o >>= 1) { if (tid < o) sh[tid] += sh[tid + o]; __syncthreads(); }
    if (tid == 0) {
        float E = (float)(T_ * SDv);
        float var_f = __fdiv_rn((float)sh[0], E);
        g_denom[stage * 8 + b] = __fsqrt_rn(var_f + 1e-5f);
    }
}

// ---------------- fused BN + IF over Q,V,K with CARRIED membrane ----------------
__global__ void k_ifqvk() {
    int j = blockIdx.x * 256 + threadIdx.x;
    if (j >= BSD_) return;
    int b = j / SD_;
    float mq = g_mean[ST_Q * 8 + b], dq = g_denom[ST_Q * 8 + b];
    float mv = g_mean[ST_V * 8 + b], dv = g_denom[ST_V * 8 + b];
    float mk = g_mean[ST_K * 8 + b], dk = g_denom[ST_K * 8 + b];
    float vm = 0.0f;
#pragma unroll
    for (int t = 0; t < T_; t++) {
        int idx = t * BSD_ + j;
        vm += __fdiv_rn(g_q[idx] - mq, dq);
        float s = (vm >= 1.0f) ? 1.0f : 0.0f;
        g_qs[idx] = (u8)s;
        vm *= (1.0f - s);
    }
#pragma unroll
    for (int t = 0; t < T_; t++) {
        int idx = t * BSD_ + j;
        vm += __fdiv_rn(g_v[idx] - mv, dv);
        float s = (vm >= 1.0f) ? 1.0f : 0.0f;
        g_vs[idx] = (u8)s;
        vm *= (1.0f - s);
    }
#pragma unroll
    for (int t = 0; t < T_; t++) {
        int idx = t * BSD_ + j;
        vm += __fdiv_rn(g_k[idx] - mk, dk);
        float s = (vm >= 1.0f) ? 1.0f : 0.0f;
        g_ks[idx] = (u8)s;
        vm *= (1.0f - s);
    }
}

// ---------------- QK: integer seq-reduction (exact) ----------------
__global__ void k_qk() {
    int d = blockIdx.x * 256 + threadIdx.x;
    int tb = blockIdx.y;
    int sp = blockIdx.z;
    int acc = 0;
    int s0 = sp * 256;
    for (int s = s0; s < s0 + 256; s++) {
        size_t idx = ((size_t)tb * S_ + s) * D_ + d;
        acc += (int)(g_qs[idx] & g_ks[idx]);
    }
    g_qkp[sp * TBD_ + tb * D_ + d] = acc;
}

// QKs = IF(QK) over t (integers exact in fp32)
__global__ void k_qks() {
    int i = blockIdx.x * 256 + threadIdx.x;
    if (i >= BD_) return;
    int b = i / D_, d = i - b * D_;
    float vm = 0.0f;
#pragma unroll
    for (int t = 0; t < T_; t++) {
        int idx = (t * B_ + b) * D_ + d;
        int qk = g_qkp[idx] + g_qkp[TBD_ + idx] + g_qkp[2 * TBD_ + idx] +
                 g_qkp[3 * TBD_ + idx];
        vm += (float)qk;
        float s = (vm >= 1.0f) ? 1.0f : 0.0f;
        g_qks[idx] = (u8)s;
        vm *= (1.0f - s);
    }
}

// QKV spikes = Vs & QKs, mask emitted directly
__global__ void k_qkvm() {
    int idx = blockIdx.x * 256 + threadIdx.x;
    if (idx >= TBSD_) return;
    int lane = threadIdx.x & 31;
    int d = idx % D_;
    int tb = idx / SD_;           // t*B + b
    u8 v = g_vs[idx] & g_qks[tb * D_ + d];
    u32 bal = __ballot_sync(0xffffffffu, v != 0);
    if (lane == 0) {
        int m = idx / D_;         // == t*B*S + b*S + s
        int kw = d >> 5;
        g_msk_qkvm[(size_t)kw * MROWS_ + m] = bal;
    }
}

// h = sp + bn(att); sp2 = IF(h), mask emitted directly
__global__ void k_hsp2() {
    int j = blockIdx.x * 256 + threadIdx.x;
    if (j >= BSD_) return;
    int lane = threadIdx.x & 31;
    int b = j / SD_;
    int row = j / D_;
    int kw = (j % D_) >> 5;
    float m = g_mean[ST_ATT * 8 + b], dn = g_denom[ST_ATT * 8 + b];
    float vm = 0.0f;
#pragma unroll
    for (int t = 0; t < T_; t++) {
        int idx = t * BSD_ + j;
        float hval = (float)g_sp[idx] + __fdiv_rn(g_att[idx] - m, dn);
        g_h[idx] = hval;
        vm += hval;
        float s = (vm >= 1.0f) ? 1.0f : 0.0f;
        u32 bal = __ballot_sync(0xffffffffu, s != 0.0f);
        if (lane == 0) g_msk_sp2[(size_t)kw * MROWS_ + t * (B_ * S_) + row] = bal;
        vm *= (1.0f - s);
    }
}

// s1 = IF(bn(o1)), mask emitted directly
__global__ void k_s1() {
    int j = blockIdx.x * 256 + threadIdx.x;
    if (j >= BSH_) return;
    int lane = threadIdx.x & 31;
    int b = j / SH_;
    int row = j / HF_;
    int kw = (j % HF_) >> 5;
    float m = g_mean[ST_O1 * 8 + b], dn = g_denom[ST_O1 * 8 + b];
    float vm = 0.0f;
#pragma unroll
    for (int t = 0; t < T_; t++) {
        int idx = t * BSH_ + j;
        vm += __fdiv_rn(g_o1[idx] - m, dn);
        float s = (vm >= 1.0f) ? 1.0f : 0.0f;
        u32 bal = __ballot_sync(0xffffffffu, s != 0.0f);
        if (lane == 0) g_msk_s1[(size_t)kw * MROWS_ + t * (B_ * S_) + row] = bal;
        vm *= (1.0f - s);
    }
}

// out = h + bn(o2), float4
__global__ void k_out(float* __restrict__ out) {
    int idx4 = blockIdx.x * 256 + threadIdx.x;
    if (idx4 >= TBSD_ / 4) return;
    int idx = idx4 * 4;
    int b = (idx / SD_) % B_;
    float m = g_mean[ST_O2 * 8 + b], dn = g_denom[ST_O2 * 8 + b];
    float4 hv = *(const float4*)(g_h + idx);
    float4 ov = *(const float4*)(g_o2 + idx);
    float4 r;
    r.x = hv.x + __fdiv_rn(ov.x - m, dn);
    r.y = hv.y + __fdiv_rn(ov.y - m, dn);
    r.z = hv.z + __fdiv_rn(ov.z - m, dn);
    r.w = hv.w + __fdiv_rn(ov.w - m, dn);
    *(float4*)(out + idx) = r;
}

// ---------------- launch (kernel launches ONLY — capture-safe) ----------------
extern "C" void kernel_launch(void* const* d_in, const int* in_sizes, int n_in,
                              void* d_out, int out_size) {
    (void)in_sizes; (void)n_in; (void)out_size;
    const float* x  = (const float*)d_in[0];
    const float* wq = (const float*)d_in[1];
    const float* wk = (const float*)d_in[2];
    const float* wv = (const float*)d_in[3];
    const float* wo = (const float*)d_in[4];
    const float* w1 = (const float*)d_in[5];
    const float* b1 = (const float*)d_in[6];
    const float* w2 = (const float*)d_in[7];
    const float* b2 = (const float*)d_in[8];
    float* out = (float*)d_out;

    const int EW = 256;
    k_init_ptrs<<<1, 32>>>();

    // 1) sp = IF(x) + mask pack (fused)
    k_ifx<<<BSD_ / EW, EW>>>(x);

    // 2) Q,K,V sparse GEMMs (64-row tiles)
    sgemm12<<<dim3(6, 512), 512>>>(0, wq, nullptr, 0, D_, D_);
    sgemm12<<<dim3(6, 512), 512>>>(0, wk, nullptr, 1, D_, D_);
    sgemm12<<<dim3(6, 512), 512>>>(0, wv, nullptr, 2, D_, D_);

    // 3) BN stats (two-pass) for Q, V, K
    k_redA<<<dim3(512, 8), 256>>>(0, SD_); k_finA<<<8, 256>>>(SD_, ST_Q);
    k_redB<<<dim3(512, 8), 256>>>(0, SD_, ST_Q); k_finB<<<8, 256>>>(SD_, ST_Q);
    k_redA<<<dim3(512, 8), 256>>>(2, SD_); k_finA<<<8, 256>>>(SD_, ST_V);
    k_redB<<<dim3(512, 8), 256>>>(2, SD_, ST_V); k_finB<<<8, 256>>>(SD_, ST_V);
    k_redA<<<dim3(512, 8), 256>>>(1, SD_); k_finA<<<8, 256>>>(SD_, ST_K);
    k_redB<<<dim3(512, 8), 256>>>(1, SD_, ST_K); k_finB<<<8, 256>>>(SD_, ST_K);

    // 4) fused BN+IF, membrane carried Q -> V -> K
    k_ifqvk<<<BSD_ / EW, EW>>>();

    // 5) QK (integer) + IF + QKV spike mask (fused pack)
    k_qk<<<dim3(D_ / 256, T_ * B_, 4), 256>>>();
    k_qks<<<BD_ / EW, EW>>>();
    k_qkvm<<<TBSD_ / EW, EW>>>();

    // 6) att = QKV @ wo + BN stats
    sgemm12<<<dim3(6, 512), 512>>>(1, wo, nullptr, 3, D_, D_);
    k_redA<<<dim3(512, 8), 256>>>(3, SD_); k_finA<<<8, 256>>>(SD_, ST_ATT);
    k_redB<<<dim3(512, 8), 256>>>(3, SD_, ST_ATT); k_finB<<<8, 256>>>(SD_, ST_ATT);

    // 7) h = sp + bn(att); sp2 = IF(h) + mask pack (fused)
    k_hsp2<<<BSD_ / EW, EW>>>();

    // 8) o1 = sp2 @ w1 + b1; BN; s1 = IF(bn(o1)) + mask pack (fused)
    sgemm12<<<dim3(24, 512), 512>>>(2, w1, b1, 4, HF_, D_);
    k_redA<<<dim3(512, 8), 256>>>(4, SH_); k_finA<<<8, 256>>>(SH_, ST_O1);
    k_redB<<<dim3(512, 8), 256>>>(4, SH_, ST_O1); k_finB<<<8, 256>>>(SH_, ST_O1);
    k_s1<<<BSH_ / EW, EW>>>();

    // 9) o2 = s1 @ w2 + b2; BN
    sgemm12<<<dim3(6, 512), 512>>>(3, w2, b2, 5, D_, HF_);
    k_redA<<<dim3(512, 8), 256>>>(5, SD_); k_finA<<<8, 256>>>(SD_, ST_O2);
    k_redB<<<dim3(512, 8), 256>>>(5, SD_, ST_O2); k_finB<<<8, 256>>>(SD_, ST_O2);

    // 10) out = h + bn(o2)
    k_out<<<TBSD_ / (EW * 4), EW>>>(out);
}